// round 2
// baseline (speedup 1.0000x reference)
#include <cuda_runtime.h>
#include <cstdint>
#include <cstddef>

#define FMAXD 1024
#define GMAX  256
#define MAXN  40960

// ---------------- scratch (static device globals; no runtime allocation) ---
__device__ float g_feat[(size_t)MAXN * FMAXD];
__device__ float g_Y[(size_t)MAXN * FMAXD];
__device__ float g_Wt[(size_t)FMAXD * FMAXD];
__device__ float g_sum[GMAX * FMAXD];
__device__ float g_sq[GMAX * FMAXD];
__device__ float g_s[GMAX * FMAXD];
__device__ float g_t[GMAX * FMAXD];
__device__ int   g_cnt[GMAX];

// ---------------- helpers ---------------------------------------------------
__device__ __forceinline__ float to_tf32(float v) {
    uint32_t o;
    asm("cvt.rna.tf32.f32 %0, %1;" : "=r"(o) : "f"(v));
    return __uint_as_float(o);
}

__device__ __forceinline__ void cp16(uint32_t dst, const void* src) {
    asm volatile("cp.async.cg.shared.global [%0], [%1], 16;\n" :: "r"(dst), "l"(src));
}
__device__ __forceinline__ void cp_commit() { asm volatile("cp.async.commit_group;\n"); }
template <int n> __device__ __forceinline__ void cp_wait() {
    asm volatile("cp.async.wait_group %0;\n" :: "n"(n));
}

// ---------------- kernels ---------------------------------------------------
__global__ void zero_stats() {
    int i = blockIdx.x * blockDim.x + threadIdx.x;
    if (i < GMAX * FMAXD) { g_sum[i] = 0.f; g_sq[i] = 0.f; }
    if (i < GMAX) g_cnt[i] = 0;
}

__global__ void count_nodes(const int* __restrict__ seg, int N) {
    __shared__ int h[GMAX];
    for (int i = threadIdx.x; i < GMAX; i += blockDim.x) h[i] = 0;
    __syncthreads();
    int i = blockIdx.x * blockDim.x + threadIdx.x;
    if (i < N) atomicAdd(&h[seg[i]], 1);
    __syncthreads();
    for (int i = threadIdx.x; i < GMAX; i += blockDim.x)
        if (h[i]) atomicAdd(&g_cnt[i], h[i]);
}

// Pass 1: feat = ||feat_v + 1e-8||, accumulate per-graph sum & sumsq.
__global__ void pass1(const float* __restrict__ fv, const int* __restrict__ seg,
                      int N, int F, int npb) {
    int f  = blockIdx.x * blockDim.x + threadIdx.x;   // feature index
    int n0 = blockIdx.y * npb;
    if (n0 >= N) return;
    int nend = min(n0 + npb, N);
    float s1 = 0.f, s2 = 0.f;
    int curg = seg[n0];
    for (int n = n0; n < nend; ++n) {
        int g = seg[n];
        if (g != curg) {
            atomicAdd(&g_sum[curg * F + f], s1);
            atomicAdd(&g_sq[curg * F + f], s2);
            s1 = 0.f; s2 = 0.f; curg = g;
        }
        const float* p = fv + ((size_t)n * F + f) * 3;
        float x = p[0] + 1e-8f, y = p[1] + 1e-8f, z = p[2] + 1e-8f;
        float ft = sqrtf(fmaf(x, x, fmaf(y, y, z * z)));
        g_feat[(size_t)n * F + f] = ft;
        s1 += ft;
        s2 = fmaf(ft, ft, s2);
    }
    atomicAdd(&g_sum[curg * F + f], s1);
    atomicAdd(&g_sq[curg * F + f], s2);
}

// Per-(g,f) affine coefficients: y = feat*s + t
__global__ void stats(const float* __restrict__ alpha, const float* __restrict__ beta,
                      const float* __restrict__ gamma, int F) {
    int f = blockIdx.x * blockDim.x + threadIdx.x;
    int g = blockIdx.y;
    int c = g_cnt[g];
    if (c == 0) return;
    float invc = 1.f / (float)c;
    size_t idx = (size_t)g * F + f;
    float u  = g_sum[idx] * invc;
    float u2 = alpha[f] * u;
    float m2 = g_sq[idx] * invc;
    float sigma = m2 - 2.f * u2 * u + u2 * u2;     // E[(x-u2)^2]
    float sn = sqrtf(sigma + 1e-6f);
    float iv = 1.f / (sn + 1e-6f);
    float sv = gamma[f] * iv;
    g_s[idx] = sv;
    g_t[idx] = fmaf(-u2, sv, beta[f]);
}

// Y = feat*s + t, rounded to tf32
__global__ void make_y(const int* __restrict__ seg, int N, int F) {
    int q = F / 4;
    long long i = (long long)blockIdx.x * blockDim.x + threadIdx.x;
    if (i >= (long long)N * q) return;
    int n = (int)(i / q);
    int j = (int)(i % q);
    int g = seg[n];
    float4 ft = reinterpret_cast<const float4*>(g_feat)[(size_t)n * q + j];
    float4 sv = reinterpret_cast<const float4*>(g_s)[(size_t)g * q + j];
    float4 tv = reinterpret_cast<const float4*>(g_t)[(size_t)g * q + j];
    float4 y;
    y.x = to_tf32(fmaf(ft.x, sv.x, tv.x));
    y.y = to_tf32(fmaf(ft.y, sv.y, tv.y));
    y.z = to_tf32(fmaf(ft.z, sv.z, tv.z));
    y.w = to_tf32(fmaf(ft.w, sv.w, tv.w));
    reinterpret_cast<float4*>(g_Y)[(size_t)n * q + j] = y;
}

__global__ void conv_w(const float* __restrict__ W, int FF4) {
    int i = blockIdx.x * blockDim.x + threadIdx.x;
    if (i >= FF4) return;
    float4 w = reinterpret_cast<const float4*>(W)[i];
    float4 o;
    o.x = to_tf32(w.x); o.y = to_tf32(w.y); o.z = to_tf32(w.z); o.w = to_tf32(w.w);
    reinterpret_cast<float4*>(g_Wt)[i] = o;
}

// ---------------- GEMM (tf32 mma.sync) with fused final rescale epilogue ----
#define BM 128
#define BN 128
#define BK 32
#define STR 36
#define STAGE_SZ (BM * STR)

__global__ void __launch_bounds__(256) gemm_fused(
    const float* __restrict__ fv, const float* __restrict__ zeta,
    const float* __restrict__ bias, float* __restrict__ out, int N, int F) {
    extern __shared__ float sm[];
    float* As = sm;                         // [2][BM][STR]
    float* Bs = sm + 2 * STAGE_SZ;          // [2][BN][STR]
    int tid = threadIdx.x;
    int m0 = blockIdx.y * BM;
    int n0 = blockIdx.x * BN;
    int lr = tid / 8;       // 0..31
    int lc = tid % 8;       // float4 column
    uint32_t asBase = (uint32_t)__cvta_generic_to_shared(As);
    uint32_t bsBase = (uint32_t)__cvta_generic_to_shared(Bs);
    int NK = F / BK;

    float acc[4][4][4];
#pragma unroll
    for (int a = 0; a < 4; ++a)
#pragma unroll
        for (int b = 0; b < 4; ++b)
#pragma unroll
            for (int c2 = 0; c2 < 4; ++c2) acc[a][b][c2] = 0.f;

    int wid = tid / 32, lane = tid % 32;
    int warpM = (wid / 4) * 64;
    int warpN = (wid % 4) * 32;
    int r = lane >> 2, c = lane & 3;

    auto loadA = [&](int st, int kt) {
#pragma unroll
        for (int it = 0; it < 4; ++it) {
            int row = lr + it * 32;
            int gr = m0 + row; if (gr > N - 1) gr = N - 1;
            const float* src = g_Y + (size_t)gr * F + kt * BK + lc * 4;
            uint32_t dst = asBase + (uint32_t)(st * STAGE_SZ + row * STR + lc * 4) * 4u;
            cp16(dst, src);
        }
    };
    auto loadB = [&](int st, int kt) {
#pragma unroll
        for (int it = 0; it < 4; ++it) {
            int row = lr + it * 32;
            const float* src = g_Wt + (size_t)(n0 + row) * F + kt * BK + lc * 4;
            uint32_t dst = bsBase + (uint32_t)(st * STAGE_SZ + row * STR + lc * 4) * 4u;
            cp16(dst, src);
        }
    };

    loadA(0, 0); loadB(0, 0); cp_commit();

    for (int kt = 0; kt < NK; ++kt) {
        int st = kt & 1;
        if (kt + 1 < NK) { loadA(st ^ 1, kt + 1); loadB(st ^ 1, kt + 1); cp_commit(); cp_wait<1>(); }
        else             { cp_wait<0>(); }
        __syncthreads();
        const float* At = As + st * STAGE_SZ;
        const float* Bt = Bs + st * STAGE_SZ;
#pragma unroll
        for (int ks = 0; ks < 4; ++ks) {
            uint32_t a[4][4], bb[4][2];
#pragma unroll
            for (int mt = 0; mt < 4; ++mt) {
                const float* p = At + (warpM + mt * 16 + r) * STR + ks * 8 + c;
                a[mt][0] = __float_as_uint(p[0]);
                a[mt][1] = __float_as_uint(p[8 * STR]);
                a[mt][2] = __float_as_uint(p[4]);
                a[mt][3] = __float_as_uint(p[8 * STR + 4]);
            }
#pragma unroll
            for (int nt = 0; nt < 4; ++nt) {
                const float* p = Bt + (warpN + nt * 8 + r) * STR + ks * 8 + c;
                bb[nt][0] = __float_as_uint(p[0]);
                bb[nt][1] = __float_as_uint(p[4]);
            }
#pragma unroll
            for (int mt = 0; mt < 4; ++mt)
#pragma unroll
                for (int nt = 0; nt < 4; ++nt)
                    asm volatile(
                        "mma.sync.aligned.m16n8k8.row.col.f32.tf32.tf32.f32 "
                        "{%0,%1,%2,%3},{%4,%5,%6,%7},{%8,%9},{%0,%1,%2,%3};\n"
                        : "+f"(acc[mt][nt][0]), "+f"(acc[mt][nt][1]),
                          "+f"(acc[mt][nt][2]), "+f"(acc[mt][nt][3])
                        : "r"(a[mt][0]), "r"(a[mt][1]), "r"(a[mt][2]), "r"(a[mt][3]),
                          "r"(bb[nt][0]), "r"(bb[nt][1]));
        }
        __syncthreads();
    }

    // Fused epilogue: gate = acc + b[j]; out[n,j,:] = gate * fv[n,j,:]/(feat[n,j]+zeta[j]+1e-8)
#pragma unroll
    for (int mt = 0; mt < 4; ++mt) {
#pragma unroll
        for (int half = 0; half < 2; ++half) {
            int n = m0 + warpM + mt * 16 + r + half * 8;
            if (n >= N) continue;
#pragma unroll
            for (int nt = 0; nt < 4; ++nt) {
                int j = n0 + warpN + nt * 8 + 2 * c;
                float d0 = acc[mt][nt][half * 2 + 0];
                float d1 = acc[mt][nt][half * 2 + 1];
                float2 ft = *reinterpret_cast<const float2*>(&g_feat[(size_t)n * F + j]);
                float gt0 = d0 + bias[j];
                float gt1 = d1 + bias[j + 1];
                float s0 = gt0 / (ft.x + zeta[j] + 1e-8f);
                float s1 = gt1 / (ft.y + zeta[j + 1] + 1e-8f);
                size_t base = ((size_t)n * F + j) * 3;
                const float2* vp = reinterpret_cast<const float2*>(fv + base);
                float2* op = reinterpret_cast<float2*>(out + base);
                float2 v0 = vp[0], v1 = vp[1], v2 = vp[2];
                float2 o0, o1, o2;
                o0.x = s0 * v0.x; o0.y = s0 * v0.y;   // (j,c0),(j,c1)
                o1.x = s0 * v1.x; o1.y = s1 * v1.y;   // (j,c2),(j+1,c0)
                o2.x = s1 * v2.x; o2.y = s1 * v2.y;   // (j+1,c1),(j+1,c2)
                op[0] = o0; op[1] = o1; op[2] = o2;
            }
        }
    }
}

// ---------------- launch -----------------------------------------------------
extern "C" void kernel_launch(void* const* d_in, const int* in_sizes, int n_in,
                              void* d_out, int out_size) {
    int o = (n_in >= 9) ? 3 : 2;   // skip num_graphs scalar if present
    const float* fv    = (const float*)d_in[0];
    const int*   seg   = (const int*)d_in[1];
    const float* alpha = (const float*)d_in[o];
    const float* beta  = (const float*)d_in[o + 1];
    const float* gamma = (const float*)d_in[o + 2];
    const float* zeta  = (const float*)d_in[o + 3];
    const float* W     = (const float*)d_in[o + 4];
    const float* bias  = (const float*)d_in[o + 5];
    int F = in_sizes[o];
    int N = in_sizes[0] / (3 * F);
    float* out = (float*)d_out;

    zero_stats<<<(GMAX * FMAXD + 255) / 256, 256>>>();
    count_nodes<<<(N + 255) / 256, 256>>>(seg, N);

    int npb = 125;
    dim3 g1(F / 256, (N + npb - 1) / npb);
    pass1<<<g1, 256>>>(fv, seg, N, F, npb);

    dim3 g2(F / 256, GMAX);
    stats<<<g2, 256>>>(alpha, beta, gamma, F);

    long long yq = (long long)N * (F / 4);
    make_y<<<(unsigned)((yq + 255) / 256), 256>>>(seg, N, F);
    conv_w<<<(F * F / 4 + 255) / 256, 256>>>(W, F * F / 4);

    cudaFuncSetAttribute(gemm_fused, cudaFuncAttributeMaxDynamicSharedMemorySize, 73728);
    dim3 gg(F / BN, (N + BM - 1) / BM);
    gemm_fused<<<gg, 256, 73728>>>(fv, zeta, bias, out, N, F);
}

// round 5
// speedup vs baseline: 1.2689x; 1.2689x over previous
#include <cuda_runtime.h>
#include <cuda_fp16.h>
#include <cstdint>
#include <cstddef>

#define FMAXD 1024
#define GMAX  256
#define MAXN  40960

// ---------------- scratch (static device globals; no runtime allocation) ---
__device__ float  g_feat[(size_t)MAXN * FMAXD];
__device__ __half g_Yh[(size_t)MAXN * FMAXD];
__device__ __half g_Wh[(size_t)FMAXD * FMAXD];
__device__ float  g_sum[GMAX * FMAXD];
__device__ float  g_sq[GMAX * FMAXD];
__device__ float  g_s[GMAX * FMAXD];
__device__ float  g_t[GMAX * FMAXD];
__device__ int    g_cnt[GMAX];

// ---------------- helpers ---------------------------------------------------
__device__ __forceinline__ void cp16(uint32_t dst, const void* src) {
    asm volatile("cp.async.cg.shared.global [%0], [%1], 16;\n" :: "r"(dst), "l"(src));
}
__device__ __forceinline__ void cp_commit() { asm volatile("cp.async.commit_group;\n"); }
template <int n> __device__ __forceinline__ void cp_wait() {
    asm volatile("cp.async.wait_group %0;\n" :: "n"(n));
}

// ---------------- small kernels ---------------------------------------------
__global__ void zero_stats() {
    int i = blockIdx.x * blockDim.x + threadIdx.x;
    if (i < GMAX * FMAXD) { g_sum[i] = 0.f; g_sq[i] = 0.f; }
    if (i < GMAX) g_cnt[i] = 0;
}

__global__ void count_nodes(const int* __restrict__ seg, int N) {
    __shared__ int h[GMAX];
    for (int i = threadIdx.x; i < GMAX; i += blockDim.x) h[i] = 0;
    __syncthreads();
    int i = blockIdx.x * blockDim.x + threadIdx.x;
    if (i < N) atomicAdd(&h[seg[i]], 1);
    __syncthreads();
    for (int i = threadIdx.x; i < GMAX; i += blockDim.x)
        if (h[i]) atomicAdd(&g_cnt[i], h[i]);
}

// Pass 1: feat = ||feat_v + 1e-8||, accumulate per-graph sum & sumsq.
__global__ void pass1(const float* __restrict__ fv, const int* __restrict__ seg,
                      int N, int F, int npb) {
    int f  = blockIdx.x * blockDim.x + threadIdx.x;
    int n0 = blockIdx.y * npb;
    if (n0 >= N) return;
    int nend = min(n0 + npb, N);
    float s1 = 0.f, s2 = 0.f;
    int curg = seg[n0];
    for (int n = n0; n < nend; ++n) {
        int g = seg[n];
        if (g != curg) {
            atomicAdd(&g_sum[curg * F + f], s1);
            atomicAdd(&g_sq[curg * F + f], s2);
            s1 = 0.f; s2 = 0.f; curg = g;
        }
        const float* p = fv + ((size_t)n * F + f) * 3;
        float x = p[0] + 1e-8f, y = p[1] + 1e-8f, z = p[2] + 1e-8f;
        float ft = sqrtf(fmaf(x, x, fmaf(y, y, z * z)));
        g_feat[(size_t)n * F + f] = ft;
        s1 += ft;
        s2 = fmaf(ft, ft, s2);
    }
    atomicAdd(&g_sum[curg * F + f], s1);
    atomicAdd(&g_sq[curg * F + f], s2);
}

// Per-(g,f) affine coefficients: y = feat*s + t
__global__ void stats(const float* __restrict__ alpha, const float* __restrict__ beta,
                      const float* __restrict__ gamma, int F) {
    int f = blockIdx.x * blockDim.x + threadIdx.x;
    int g = blockIdx.y;
    int c = g_cnt[g];
    if (c == 0) return;
    float invc = 1.f / (float)c;
    size_t idx = (size_t)g * F + f;
    float u  = g_sum[idx] * invc;
    float u2 = alpha[f] * u;
    float m2 = g_sq[idx] * invc;
    float sigma = m2 - 2.f * u2 * u + u2 * u2;
    float sn = sqrtf(sigma + 1e-6f);
    float iv = 1.f / (sn + 1e-6f);
    float sv = gamma[f] * iv;
    g_s[idx] = sv;
    g_t[idx] = fmaf(-u2, sv, beta[f]);
}

// Y = feat*s + t, cast to fp16
__global__ void make_y(const int* __restrict__ seg, int N, int F) {
    int q = F / 4;
    long long i = (long long)blockIdx.x * blockDim.x + threadIdx.x;
    if (i >= (long long)N * q) return;
    int n = (int)(i / q);
    int j = (int)(i % q);
    int g = seg[n];
    float4 ft = reinterpret_cast<const float4*>(g_feat)[(size_t)n * q + j];
    float4 sv = reinterpret_cast<const float4*>(g_s)[(size_t)g * q + j];
    float4 tv = reinterpret_cast<const float4*>(g_t)[(size_t)g * q + j];
    __half2 y01, y23;
    y01.x = __float2half(fmaf(ft.x, sv.x, tv.x));
    y01.y = __float2half(fmaf(ft.y, sv.y, tv.y));
    y23.x = __float2half(fmaf(ft.z, sv.z, tv.z));
    y23.y = __float2half(fmaf(ft.w, sv.w, tv.w));
    __half2* dst = reinterpret_cast<__half2*>(g_Yh + (size_t)n * F + 4 * j);
    dst[0] = y01; dst[1] = y23;
}

__global__ void conv_w(const float* __restrict__ W, int total4) {
    int i = blockIdx.x * blockDim.x + threadIdx.x;
    if (i >= total4) return;
    float4 w = reinterpret_cast<const float4*>(W)[i];
    __half2 h01, h23;
    h01.x = __float2half(w.x); h01.y = __float2half(w.y);
    h23.x = __float2half(w.z); h23.y = __float2half(w.w);
    __half2* dst = reinterpret_cast<__half2*>(g_Wh + (size_t)4 * i);
    dst[0] = h01; dst[1] = h23;
}

// ---------------- fp16 mma.sync GEMM with fused final rescale epilogue ------
#define BM 128
#define BN 128
#define BK 64
// row stride in halfs: 64 data + 8 pad = 72 halfs = 144 bytes
#define RSTR 72
#define STAGE_H (BM * RSTR)            // halfs per A (or B) stage
#define NSTAGE 3

__global__ void __launch_bounds__(256, 1) gemm_fused(
    const float* __restrict__ fv, const float* __restrict__ zeta,
    const float* __restrict__ bias, float* __restrict__ out, int N, int F) {
    extern __shared__ __half sm[];
    __half* As = sm;                        // [NSTAGE][BM][RSTR]
    __half* Bs = sm + NSTAGE * STAGE_H;     // [NSTAGE][BN][RSTR]
    int tid = threadIdx.x;
    int m0 = blockIdx.y * BM;
    int n0 = blockIdx.x * BN;
    uint32_t asBase = (uint32_t)__cvta_generic_to_shared(As);
    uint32_t bsBase = (uint32_t)__cvta_generic_to_shared(Bs);
    int NK = F / BK;                        // 16

    float acc[4][4][4];
#pragma unroll
    for (int a = 0; a < 4; ++a)
#pragma unroll
        for (int b = 0; b < 4; ++b)
#pragma unroll
            for (int c2 = 0; c2 < 4; ++c2) acc[a][b][c2] = 0.f;

    int wid = tid / 32, lane = tid % 32;
    int warpM = (wid / 4) * 64;             // 2 warp rows
    int warpN = (wid % 4) * 32;             // 4 warp cols
    int r = lane >> 2, c = lane & 3;

    // per-thread load mapping: 1024 16B-chunks per operand per kt, 4 per thread
    auto loadAB = [&](int st, int kt) {
#pragma unroll
        for (int it = 0; it < 4; ++it) {
            int id = tid + 256 * it;        // 0..1023
            int row = id >> 3, ch = id & 7; // 8 chunks of 16B per row
            // A
            int gr = m0 + row; if (gr > N - 1) gr = N - 1;
            const void* srcA = g_Yh + (size_t)gr * F + kt * BK + ch * 8;
            cp16(asBase + (uint32_t)(st * STAGE_H + row * RSTR) * 2u + ch * 16u, srcA);
            // B
            const void* srcB = g_Wh + (size_t)(n0 + row) * F + kt * BK + ch * 8;
            cp16(bsBase + (uint32_t)(st * STAGE_H + row * RSTR) * 2u + ch * 16u, srcB);
        }
    };

    loadAB(0, 0); cp_commit();
    loadAB(1, 1); cp_commit();
    loadAB(2, 2); cp_commit();

    int l8 = lane & 7, lg = lane >> 3;      // ldmatrix lane grouping

    for (int kt = 0; kt < NK; ++kt) {
        int st = kt % NSTAGE;
        cp_wait<2>();
        __syncthreads();
        const __half* At = As + st * STAGE_H;
        const __half* Bt = Bs + st * STAGE_H;
#pragma unroll
        for (int ks = 0; ks < 4; ++ks) {    // 4 k16-steps per BK=64
            uint32_t a[4][4], bb[4][2];
            // A frags: 4 x ldmatrix.x4 (16x16 each)
#pragma unroll
            for (int mt = 0; mt < 4; ++mt) {
                // address groups: g0:(m+l8,k0) g1:(m+8+l8,k0) g2:(m+l8,k8) g3:(m+8+l8,k8)
                int arow = warpM + mt * 16 + ((lg & 1) ? 8 : 0) + l8;
                int acol = ks * 16 + ((lg >> 1) ? 8 : 0);
                uint32_t addr = (uint32_t)__cvta_generic_to_shared(At + arow * RSTR + acol);
                asm volatile("ldmatrix.sync.aligned.m8n8.x4.shared.b16 {%0,%1,%2,%3}, [%4];"
                             : "=r"(a[mt][0]), "=r"(a[mt][1]), "=r"(a[mt][2]), "=r"(a[mt][3])
                             : "r"(addr));
            }
            // B frags: smem is [n][k] (k contiguous) == exactly the mma B layout,
            // so use NON-trans ldmatrix. x4 covers 16 n-rows x 16 k-cols.
#pragma unroll
            for (int pp = 0; pp < 2; ++pp) {
                // address groups: g0:(n+l8,k0) g1:(n+l8,k8) g2:(n+8+l8,k0) g3:(n+8+l8,k8)
                int brow = warpN + pp * 16 + ((lg >> 1) ? 8 : 0) + l8;
                int bcol = ks * 16 + ((lg & 1) ? 8 : 0);
                uint32_t addr = (uint32_t)__cvta_generic_to_shared(Bt + brow * RSTR + bcol);
                uint32_t r0, r1, r2, r3;
                asm volatile("ldmatrix.sync.aligned.m8n8.x4.shared.b16 {%0,%1,%2,%3}, [%4];"
                             : "=r"(r0), "=r"(r1), "=r"(r2), "=r"(r3) : "r"(addr));
                bb[pp * 2 + 0][0] = r0; bb[pp * 2 + 0][1] = r1;
                bb[pp * 2 + 1][0] = r2; bb[pp * 2 + 1][1] = r3;
            }
#pragma unroll
            for (int mt = 0; mt < 4; ++mt)
#pragma unroll
                for (int nt = 0; nt < 4; ++nt)
                    asm volatile(
                        "mma.sync.aligned.m16n8k16.row.col.f32.f16.f16.f32 "
                        "{%0,%1,%2,%3},{%4,%5,%6,%7},{%8,%9},{%0,%1,%2,%3};\n"
                        : "+f"(acc[mt][nt][0]), "+f"(acc[mt][nt][1]),
                          "+f"(acc[mt][nt][2]), "+f"(acc[mt][nt][3])
                        : "r"(a[mt][0]), "r"(a[mt][1]), "r"(a[mt][2]), "r"(a[mt][3]),
                          "r"(bb[nt][0]), "r"(bb[nt][1]));
        }
        __syncthreads();
        if (kt + NSTAGE < NK) { loadAB(st, kt + NSTAGE); cp_commit(); }
    }
    cp_wait<0>();

    // Fused epilogue: gate = acc + b[j]; out[n,j,:] = gate * fv[n,j,:]/(feat[n,j]+zeta[j]+1e-8)
#pragma unroll
    for (int mt = 0; mt < 4; ++mt) {
#pragma unroll
        for (int half = 0; half < 2; ++half) {
            int n = m0 + warpM + mt * 16 + r + half * 8;
            if (n >= N) continue;
#pragma unroll
            for (int nt = 0; nt < 4; ++nt) {
                int j = n0 + warpN + nt * 8 + 2 * c;
                float d0 = acc[mt][nt][half * 2 + 0];
                float d1 = acc[mt][nt][half * 2 + 1];
                float2 ft = *reinterpret_cast<const float2*>(&g_feat[(size_t)n * F + j]);
                float gt0 = d0 + bias[j];
                float gt1 = d1 + bias[j + 1];
                float s0 = gt0 / (ft.x + zeta[j] + 1e-8f);
                float s1 = gt1 / (ft.y + zeta[j + 1] + 1e-8f);
                size_t base = ((size_t)n * F + j) * 3;
                const float2* vp = reinterpret_cast<const float2*>(fv + base);
                float2* op = reinterpret_cast<float2*>(out + base);
                float2 v0 = vp[0], v1 = vp[1], v2 = vp[2];
                float2 o0, o1, o2;
                o0.x = s0 * v0.x; o0.y = s0 * v0.y;
                o1.x = s0 * v1.x; o1.y = s1 * v1.y;
                o2.x = s1 * v2.x; o2.y = s1 * v2.y;
                op[0] = o0; op[1] = o1; op[2] = o2;
            }
        }
    }
}

// ---------------- launch -----------------------------------------------------
extern "C" void kernel_launch(void* const* d_in, const int* in_sizes, int n_in,
                              void* d_out, int out_size) {
    int o = (n_in >= 9) ? 3 : 2;
    const float* fv    = (const float*)d_in[0];
    const int*   seg   = (const int*)d_in[1];
    const float* alpha = (const float*)d_in[o];
    const float* beta  = (const float*)d_in[o + 1];
    const float* gamma = (const float*)d_in[o + 2];
    const float* zeta  = (const float*)d_in[o + 3];
    const float* W     = (const float*)d_in[o + 4];
    const float* bias  = (const float*)d_in[o + 5];
    int F = in_sizes[o];
    int N = in_sizes[0] / (3 * F);
    float* out = (float*)d_out;

    zero_stats<<<(GMAX * FMAXD + 255) / 256, 256>>>();
    count_nodes<<<(N + 255) / 256, 256>>>(seg, N);

    int npb = 125;
    dim3 g1(F / 256, (N + npb - 1) / npb);
    pass1<<<g1, 256>>>(fv, seg, N, F, npb);

    dim3 g2(F / 256, GMAX);
    stats<<<g2, 256>>>(alpha, beta, gamma, F);

    long long yq = (long long)N * (F / 4);
    make_y<<<(unsigned)((yq + 255) / 256), 256>>>(seg, N, F);
    conv_w<<<(F * F / 4 + 255) / 256, 256>>>(W, F * F / 4);

    size_t smem = (size_t)NSTAGE * 2 * BM * RSTR * sizeof(__half);  // 110592
    cudaFuncSetAttribute(gemm_fused, cudaFuncAttributeMaxDynamicSharedMemorySize, (int)smem);
    dim3 gg(F / BN, (N + BM - 1) / BM);
    gemm_fused<<<gg, 256, smem>>>(fv, zeta, bias, out, N, F);
}

// round 7
// speedup vs baseline: 1.6855x; 1.3283x over previous
#include <cuda_runtime.h>
#include <cuda_fp16.h>
#include <cstdint>
#include <cstddef>

#define FMAXD 1024
#define GMAX  256
#define MAXN  40960

// ---------------- scratch (static device globals; no runtime allocation) ---
__device__ float  g_feat[(size_t)MAXN * FMAXD];
__device__ __half g_Yh[(size_t)MAXN * FMAXD];
__device__ __half g_Wh[(size_t)FMAXD * FMAXD];
__device__ float  g_sum[GMAX * FMAXD];
__device__ float  g_sq[GMAX * FMAXD];
__device__ float  g_s[GMAX * FMAXD];
__device__ float  g_t[GMAX * FMAXD];
__device__ int    g_cnt[GMAX];

// ---------------- helpers ---------------------------------------------------
__device__ __forceinline__ void cp16(uint32_t dst, const void* src) {
    asm volatile("cp.async.cg.shared.global [%0], [%1], 16;\n" :: "r"(dst), "l"(src));
}
__device__ __forceinline__ void cp_commit() { asm volatile("cp.async.commit_group;\n"); }
template <int n> __device__ __forceinline__ void cp_wait() {
    asm volatile("cp.async.wait_group %0;\n" :: "n"(n));
}

// ---------------- small kernels ---------------------------------------------
__global__ void zero_stats() {
    int i = blockIdx.x * blockDim.x + threadIdx.x;
    if (i < GMAX * FMAXD) { g_sum[i] = 0.f; g_sq[i] = 0.f; }
    if (i < GMAX) g_cnt[i] = 0;
}

__global__ void count_nodes(const int* __restrict__ seg, int N) {
    __shared__ int h[GMAX];
    for (int i = threadIdx.x; i < GMAX; i += blockDim.x) h[i] = 0;
    __syncthreads();
    int i = blockIdx.x * blockDim.x + threadIdx.x;
    if (i < N) atomicAdd(&h[seg[i]], 1);
    __syncthreads();
    for (int i = threadIdx.x; i < GMAX; i += blockDim.x)
        if (h[i]) atomicAdd(&g_cnt[i], h[i]);
}

// Pass 1 (vectorized): each thread owns a feature-quad. 12 contiguous floats
// = 4 features x 3 comps = 3 x float4 loads, 1 x float4 feat store.
__global__ void pass1(const float* __restrict__ fv, const int* __restrict__ seg,
                      int N, int F, int npb) {
    int q  = blockIdx.x * blockDim.x + threadIdx.x;   // feature quad
    if (q >= F / 4) return;
    int n0 = blockIdx.y * npb;
    if (n0 >= N) return;
    int nend = min(n0 + npb, N);
    float s1[4] = {0.f, 0.f, 0.f, 0.f};
    float s2[4] = {0.f, 0.f, 0.f, 0.f};
    int curg = seg[n0];
    int f0 = 4 * q;
    for (int n = n0; n < nend; ++n) {
        int g = seg[n];
        if (g != curg) {
#pragma unroll
            for (int k = 0; k < 4; ++k) {
                atomicAdd(&g_sum[curg * F + f0 + k], s1[k]);
                atomicAdd(&g_sq[curg * F + f0 + k], s2[k]);
                s1[k] = 0.f; s2[k] = 0.f;
            }
            curg = g;
        }
        const float4* p = reinterpret_cast<const float4*>(fv + ((size_t)n * F + f0) * 3);
        float4 a = p[0], b = p[1], c = p[2];
        float x0 = a.x + 1e-8f, y0 = a.y + 1e-8f, z0 = a.z + 1e-8f;
        float x1 = a.w + 1e-8f, y1 = b.x + 1e-8f, z1 = b.y + 1e-8f;
        float x2 = b.z + 1e-8f, y2 = b.w + 1e-8f, z2 = c.x + 1e-8f;
        float x3 = c.y + 1e-8f, y3 = c.z + 1e-8f, z3 = c.w + 1e-8f;
        float4 ft;
        ft.x = sqrtf(fmaf(x0, x0, fmaf(y0, y0, z0 * z0)));
        ft.y = sqrtf(fmaf(x1, x1, fmaf(y1, y1, z1 * z1)));
        ft.z = sqrtf(fmaf(x2, x2, fmaf(y2, y2, z2 * z2)));
        ft.w = sqrtf(fmaf(x3, x3, fmaf(y3, y3, z3 * z3)));
        reinterpret_cast<float4*>(g_feat + (size_t)n * F + f0)[0] = ft;
        s1[0] += ft.x; s2[0] = fmaf(ft.x, ft.x, s2[0]);
        s1[1] += ft.y; s2[1] = fmaf(ft.y, ft.y, s2[1]);
        s1[2] += ft.z; s2[2] = fmaf(ft.z, ft.z, s2[2]);
        s1[3] += ft.w; s2[3] = fmaf(ft.w, ft.w, s2[3]);
    }
#pragma unroll
    for (int k = 0; k < 4; ++k) {
        atomicAdd(&g_sum[curg * F + f0 + k], s1[k]);
        atomicAdd(&g_sq[curg * F + f0 + k], s2[k]);
    }
}

// Per-(g,f) affine coefficients: y = feat*s + t
__global__ void stats(const float* __restrict__ alpha, const float* __restrict__ beta,
                      const float* __restrict__ gamma, int F) {
    int f = blockIdx.x * blockDim.x + threadIdx.x;
    int g = blockIdx.y;
    int c = g_cnt[g];
    if (c == 0) return;
    float invc = 1.f / (float)c;
    size_t idx = (size_t)g * F + f;
    float u  = g_sum[idx] * invc;
    float u2 = alpha[f] * u;
    float m2 = g_sq[idx] * invc;
    float sigma = m2 - 2.f * u2 * u + u2 * u2;
    float sn = sqrtf(sigma + 1e-6f);
    float iv = 1.f / (sn + 1e-6f);
    float sv = gamma[f] * iv;
    g_s[idx] = sv;
    g_t[idx] = fmaf(-u2, sv, beta[f]);
}

// Y = feat*s + t, cast to fp16
__global__ void make_y(const int* __restrict__ seg, int N, int F) {
    int q = F / 4;
    long long i = (long long)blockIdx.x * blockDim.x + threadIdx.x;
    if (i >= (long long)N * q) return;
    int n = (int)(i / q);
    int j = (int)(i % q);
    int g = seg[n];
    float4 ft = reinterpret_cast<const float4*>(g_feat)[(size_t)n * q + j];
    float4 sv = reinterpret_cast<const float4*>(g_s)[(size_t)g * q + j];
    float4 tv = reinterpret_cast<const float4*>(g_t)[(size_t)g * q + j];
    __half2 y01, y23;
    y01.x = __float2half(fmaf(ft.x, sv.x, tv.x));
    y01.y = __float2half(fmaf(ft.y, sv.y, tv.y));
    y23.x = __float2half(fmaf(ft.z, sv.z, tv.z));
    y23.y = __float2half(fmaf(ft.w, sv.w, tv.w));
    __half2* dst = reinterpret_cast<__half2*>(g_Yh + (size_t)n * F + 4 * j);
    dst[0] = y01; dst[1] = y23;
}

__global__ void conv_w(const float* __restrict__ W, int total4) {
    int i = blockIdx.x * blockDim.x + threadIdx.x;
    if (i >= total4) return;
    float4 w = reinterpret_cast<const float4*>(W)[i];
    __half2 h01, h23;
    h01.x = __float2half(w.x); h01.y = __float2half(w.y);
    h23.x = __float2half(w.z); h23.y = __float2half(w.w);
    __half2* dst = reinterpret_cast<__half2*>(g_Wh + (size_t)4 * i);
    dst[0] = h01; dst[1] = h23;
}

// ---------------- fp16 mma.sync GEMM with fused final rescale epilogue ------
// BM=128, BN=64, warp tile 32x32 -> acc 32 regs -> 2 CTAs/SM.
#define BM 128
#define BN 64
#define BK 64
#define RSTR 72                          // 64 data + 8 pad halfs (144B rows)
#define A_STG (BM * RSTR)                // 9216 halfs
#define B_STG (BN * RSTR)                // 4608 halfs
#define NSTAGE 3
#define SMEM_B ((NSTAGE * (A_STG + B_STG)) * 2)   // 82944 bytes

__global__ void __launch_bounds__(256, 2) gemm_fused(
    const float* __restrict__ fv, const float* __restrict__ zeta,
    const float* __restrict__ bias, float* __restrict__ out, int N, int F) {
    extern __shared__ __half sm[];
    __half* As = sm;                        // [NSTAGE][BM][RSTR]
    __half* Bs = sm + NSTAGE * A_STG;       // [NSTAGE][BN][RSTR]
    int tid = threadIdx.x;
    int m0 = blockIdx.y * BM;
    int n0 = blockIdx.x * BN;
    uint32_t asBase = (uint32_t)__cvta_generic_to_shared(As);
    uint32_t bsBase = (uint32_t)__cvta_generic_to_shared(Bs);
    int NK = F / BK;                        // 16

    float acc[2][4][4];
#pragma unroll
    for (int a = 0; a < 2; ++a)
#pragma unroll
        for (int b = 0; b < 4; ++b)
#pragma unroll
            for (int c2 = 0; c2 < 4; ++c2) acc[a][b][c2] = 0.f;

    int wid = tid / 32, lane = tid % 32;
    int warpM = (wid >> 1) * 32;            // 4 warp rows
    int warpN = (wid & 1) * 32;             // 2 warp cols
    int r = lane >> 2, c = lane & 3;

    auto loadAB = [&](int st, int kt) {
#pragma unroll
        for (int it = 0; it < 4; ++it) {    // A: 1024 chunks
            int id = tid + 256 * it;
            int row = id >> 3, ch = id & 7;
            int gr = m0 + row; if (gr > N - 1) gr = N - 1;
            const void* srcA = g_Yh + (size_t)gr * F + kt * BK + ch * 8;
            cp16(asBase + (uint32_t)(st * A_STG + row * RSTR) * 2u + ch * 16u, srcA);
        }
#pragma unroll
        for (int it = 0; it < 2; ++it) {    // B: 512 chunks
            int id = tid + 256 * it;
            int row = id >> 3, ch = id & 7;
            const void* srcB = g_Wh + (size_t)(n0 + row) * F + kt * BK + ch * 8;
            cp16(bsBase + (uint32_t)(st * B_STG + row * RSTR) * 2u + ch * 16u, srcB);
        }
    };

    loadAB(0, 0); cp_commit();
    loadAB(1, 1); cp_commit();
    loadAB(2, 2); cp_commit();

    int l8 = lane & 7, lg = lane >> 3;      // ldmatrix lane grouping

    for (int kt = 0; kt < NK; ++kt) {
        int st = kt % NSTAGE;
        // Commits happen EVERY iteration (possibly empty groups in the tail),
        // so before this wait, committed = 3 + kt groups; wait_group 2 leaves
        // at most the 2 newest pending => groups 0..kt (data for this kt) are
        // guaranteed complete. (Tail race fixed vs previous round.)
        cp_wait<2>();
        __syncthreads();
        const __half* At = As + st * A_STG;
        const __half* Bt = Bs + st * B_STG;
#pragma unroll
        for (int ks = 0; ks < 4; ++ks) {    // 4 k16-steps per BK=64
            uint32_t a[2][4], bb[4][2];
#pragma unroll
            for (int mt = 0; mt < 2; ++mt) {
                int arow = warpM + mt * 16 + ((lg & 1) ? 8 : 0) + l8;
                int acol = ks * 16 + ((lg >> 1) ? 8 : 0);
                uint32_t addr = (uint32_t)__cvta_generic_to_shared(At + arow * RSTR + acol);
                asm volatile("ldmatrix.sync.aligned.m8n8.x4.shared.b16 {%0,%1,%2,%3}, [%4];"
                             : "=r"(a[mt][0]), "=r"(a[mt][1]), "=r"(a[mt][2]), "=r"(a[mt][3])
                             : "r"(addr));
            }
#pragma unroll
            for (int pp = 0; pp < 2; ++pp) {
                int brow = warpN + pp * 16 + ((lg >> 1) ? 8 : 0) + l8;
                int bcol = ks * 16 + ((lg & 1) ? 8 : 0);
                uint32_t addr = (uint32_t)__cvta_generic_to_shared(Bt + brow * RSTR + bcol);
                uint32_t r0, r1, r2, r3;
                asm volatile("ldmatrix.sync.aligned.m8n8.x4.shared.b16 {%0,%1,%2,%3}, [%4];"
                             : "=r"(r0), "=r"(r1), "=r"(r2), "=r"(r3) : "r"(addr));
                bb[pp * 2 + 0][0] = r0; bb[pp * 2 + 0][1] = r1;
                bb[pp * 2 + 1][0] = r2; bb[pp * 2 + 1][1] = r3;
            }
#pragma unroll
            for (int mt = 0; mt < 2; ++mt)
#pragma unroll
                for (int nt = 0; nt < 4; ++nt)
                    asm volatile(
                        "mma.sync.aligned.m16n8k16.row.col.f32.f16.f16.f32 "
                        "{%0,%1,%2,%3},{%4,%5,%6,%7},{%8,%9},{%0,%1,%2,%3};\n"
                        : "+f"(acc[mt][nt][0]), "+f"(acc[mt][nt][1]),
                          "+f"(acc[mt][nt][2]), "+f"(acc[mt][nt][3])
                        : "r"(a[mt][0]), "r"(a[mt][1]), "r"(a[mt][2]), "r"(a[mt][3]),
                          "r"(bb[nt][0]), "r"(bb[nt][1]));
        }
        __syncthreads();
        if (kt + NSTAGE < NK) loadAB(st, kt + NSTAGE);
        cp_commit();                         // ALWAYS commit (empty group in tail)
    }
    cp_wait<0>();

    // Fused epilogue: gate = acc + b[j]; out[n,j,:] = gate * fv[n,j,:]/(feat[n,j]+zeta[j]+1e-8)
#pragma unroll
    for (int mt = 0; mt < 2; ++mt) {
#pragma unroll
        for (int half = 0; half < 2; ++half) {
            int n = m0 + warpM + mt * 16 + r + half * 8;
            if (n >= N) continue;
#pragma unroll
            for (int nt = 0; nt < 4; ++nt) {
                int j = n0 + warpN + nt * 8 + 2 * c;
                float d0 = acc[mt][nt][half * 2 + 0];
                float d1 = acc[mt][nt][half * 2 + 1];
                float2 ft = *reinterpret_cast<const float2*>(&g_feat[(size_t)n * F + j]);
                float gt0 = d0 + bias[j];
                float gt1 = d1 + bias[j + 1];
                float s0 = gt0 / (ft.x + zeta[j] + 1e-8f);
                float s1 = gt1 / (ft.y + zeta[j + 1] + 1e-8f);
                size_t base = ((size_t)n * F + j) * 3;
                const float2* vp = reinterpret_cast<const float2*>(fv + base);
                float2* op = reinterpret_cast<float2*>(out + base);
                float2 v0 = vp[0], v1 = vp[1], v2 = vp[2];
                float2 o0, o1, o2;
                o0.x = s0 * v0.x; o0.y = s0 * v0.y;
                o1.x = s0 * v1.x; o1.y = s1 * v1.y;
                o2.x = s1 * v2.x; o2.y = s1 * v2.y;
                op[0] = o0; op[1] = o1; op[2] = o2;
            }
        }
    }
}

// ---------------- launch -----------------------------------------------------
extern "C" void kernel_launch(void* const* d_in, const int* in_sizes, int n_in,
                              void* d_out, int out_size) {
    int o = (n_in >= 9) ? 3 : 2;
    const float* fv    = (const float*)d_in[0];
    const int*   seg   = (const int*)d_in[1];
    const float* alpha = (const float*)d_in[o];
    const float* beta  = (const float*)d_in[o + 1];
    const float* gamma = (const float*)d_in[o + 2];
    const float* zeta  = (const float*)d_in[o + 3];
    const float* W     = (const float*)d_in[o + 4];
    const float* bias  = (const float*)d_in[o + 5];
    int F = in_sizes[o];
    int N = in_sizes[0] / (3 * F);
    float* out = (float*)d_out;

    zero_stats<<<(GMAX * FMAXD + 255) / 256, 256>>>();
    count_nodes<<<(N + 255) / 256, 256>>>(seg, N);

    int npb = 125;
    dim3 g1((F / 4 + 255) / 256, (N + npb - 1) / npb);
    pass1<<<g1, 256>>>(fv, seg, N, F, npb);

    dim3 g2(F / 256, GMAX);
    stats<<<g2, 256>>>(alpha, beta, gamma, F);

    long long yq = (long long)N * (F / 4);
    make_y<<<(unsigned)((yq + 255) / 256), 256>>>(seg, N, F);
    conv_w<<<(F * F / 4 + 255) / 256, 256>>>(W, F * F / 4);

    cudaFuncSetAttribute(gemm_fused, cudaFuncAttributeMaxDynamicSharedMemorySize, SMEM_B);
    dim3 gg(F / BN, (N + BM - 1) / BM);
    gemm_fused<<<gg, 256, SMEM_B>>>(fv, zeta, bias, out, N, F);
}

// round 8
// speedup vs baseline: 1.8198x; 1.0797x over previous
#include <cuda_runtime.h>
#include <cuda_fp16.h>
#include <cstdint>
#include <cstddef>

#define FMAXD 1024
#define GMAX  256
#define MAXN  40960

// ---------------- scratch (static device globals; no runtime allocation) ---
__device__ float  g_feat[(size_t)MAXN * FMAXD];
__device__ __half g_Yh[(size_t)MAXN * FMAXD];
__device__ __half g_Wh[(size_t)FMAXD * FMAXD];
__device__ float  g_sum[GMAX * FMAXD];
__device__ float  g_sq[GMAX * FMAXD];
__device__ float  g_s[GMAX * FMAXD];
__device__ float  g_t[GMAX * FMAXD];
__device__ int    g_cnt[GMAX];

// ---------------- helpers ---------------------------------------------------
__device__ __forceinline__ void cp16(uint32_t dst, const void* src) {
    asm volatile("cp.async.cg.shared.global [%0], [%1], 16;\n" :: "r"(dst), "l"(src));
}
__device__ __forceinline__ void cp_commit() { asm volatile("cp.async.commit_group;\n"); }
template <int n> __device__ __forceinline__ void cp_wait() {
    asm volatile("cp.async.wait_group %0;\n" :: "n"(n));
}

// ---------------- small kernels ---------------------------------------------
__global__ void zero_stats() {
    int i = blockIdx.x * blockDim.x + threadIdx.x;
    if (i < GMAX * FMAXD) { g_sum[i] = 0.f; g_sq[i] = 0.f; }
    if (i < GMAX) g_cnt[i] = 0;
}

__global__ void count_nodes(const int* __restrict__ seg, int N) {
    __shared__ int h[GMAX];
    for (int i = threadIdx.x; i < GMAX; i += blockDim.x) h[i] = 0;
    __syncthreads();
    int i = blockIdx.x * blockDim.x + threadIdx.x;
    if (i < N) atomicAdd(&h[seg[i]], 1);
    __syncthreads();
    for (int i = threadIdx.x; i < GMAX; i += blockDim.x)
        if (h[i]) atomicAdd(&g_cnt[i], h[i]);
}

// Pass 1 (vectorized): each thread owns a feature-quad. 12 contiguous floats
// = 4 features x 3 comps = 3 x float4 loads, 1 x float4 feat store.
__global__ void pass1(const float* __restrict__ fv, const int* __restrict__ seg,
                      int N, int F, int npb) {
    int q  = blockIdx.x * blockDim.x + threadIdx.x;   // feature quad
    if (q >= F / 4) return;
    int n0 = blockIdx.y * npb;
    if (n0 >= N) return;
    int nend = min(n0 + npb, N);
    float s1[4] = {0.f, 0.f, 0.f, 0.f};
    float s2[4] = {0.f, 0.f, 0.f, 0.f};
    int curg = seg[n0];
    int f0 = 4 * q;
    for (int n = n0; n < nend; ++n) {
        int g = seg[n];
        if (g != curg) {
#pragma unroll
            for (int k = 0; k < 4; ++k) {
                atomicAdd(&g_sum[curg * F + f0 + k], s1[k]);
                atomicAdd(&g_sq[curg * F + f0 + k], s2[k]);
                s1[k] = 0.f; s2[k] = 0.f;
            }
            curg = g;
        }
        const float4* p = reinterpret_cast<const float4*>(fv + ((size_t)n * F + f0) * 3);
        float4 a = p[0], b = p[1], c = p[2];
        float x0 = a.x + 1e-8f, y0 = a.y + 1e-8f, z0 = a.z + 1e-8f;
        float x1 = a.w + 1e-8f, y1 = b.x + 1e-8f, z1 = b.y + 1e-8f;
        float x2 = b.z + 1e-8f, y2 = b.w + 1e-8f, z2 = c.x + 1e-8f;
        float x3 = c.y + 1e-8f, y3 = c.z + 1e-8f, z3 = c.w + 1e-8f;
        float4 ft;
        ft.x = sqrtf(fmaf(x0, x0, fmaf(y0, y0, z0 * z0)));
        ft.y = sqrtf(fmaf(x1, x1, fmaf(y1, y1, z1 * z1)));
        ft.z = sqrtf(fmaf(x2, x2, fmaf(y2, y2, z2 * z2)));
        ft.w = sqrtf(fmaf(x3, x3, fmaf(y3, y3, z3 * z3)));
        reinterpret_cast<float4*>(g_feat + (size_t)n * F + f0)[0] = ft;
        s1[0] += ft.x; s2[0] = fmaf(ft.x, ft.x, s2[0]);
        s1[1] += ft.y; s2[1] = fmaf(ft.y, ft.y, s2[1]);
        s1[2] += ft.z; s2[2] = fmaf(ft.z, ft.z, s2[2]);
        s1[3] += ft.w; s2[3] = fmaf(ft.w, ft.w, s2[3]);
    }
#pragma unroll
    for (int k = 0; k < 4; ++k) {
        atomicAdd(&g_sum[curg * F + f0 + k], s1[k]);
        atomicAdd(&g_sq[curg * F + f0 + k], s2[k]);
    }
}

// Per-(g,f) affine coefficients: y = feat*s + t
__global__ void stats(const float* __restrict__ alpha, const float* __restrict__ beta,
                      const float* __restrict__ gamma, int F) {
    int f = blockIdx.x * blockDim.x + threadIdx.x;
    int g = blockIdx.y;
    int c = g_cnt[g];
    if (c == 0) return;
    float invc = 1.f / (float)c;
    size_t idx = (size_t)g * F + f;
    float u  = g_sum[idx] * invc;
    float u2 = alpha[f] * u;
    float m2 = g_sq[idx] * invc;
    float sigma = m2 - 2.f * u2 * u + u2 * u2;
    float sn = sqrtf(sigma + 1e-6f);
    float iv = 1.f / (sn + 1e-6f);
    float sv = gamma[f] * iv;
    g_s[idx] = sv;
    g_t[idx] = fmaf(-u2, sv, beta[f]);
}

// Y = feat*s + t, cast to fp16
__global__ void make_y(const int* __restrict__ seg, int N, int F) {
    int q = F / 4;
    long long i = (long long)blockIdx.x * blockDim.x + threadIdx.x;
    if (i >= (long long)N * q) return;
    int n = (int)(i / q);
    int j = (int)(i % q);
    int g = seg[n];
    float4 ft = reinterpret_cast<const float4*>(g_feat)[(size_t)n * q + j];
    float4 sv = reinterpret_cast<const float4*>(g_s)[(size_t)g * q + j];
    float4 tv = reinterpret_cast<const float4*>(g_t)[(size_t)g * q + j];
    __half2 y01, y23;
    y01.x = __float2half(fmaf(ft.x, sv.x, tv.x));
    y01.y = __float2half(fmaf(ft.y, sv.y, tv.y));
    y23.x = __float2half(fmaf(ft.z, sv.z, tv.z));
    y23.y = __float2half(fmaf(ft.w, sv.w, tv.w));
    __half2* dst = reinterpret_cast<__half2*>(g_Yh + (size_t)n * F + 4 * j);
    dst[0] = y01; dst[1] = y23;
}

__global__ void conv_w(const float* __restrict__ W, int total4) {
    int i = blockIdx.x * blockDim.x + threadIdx.x;
    if (i >= total4) return;
    float4 w = reinterpret_cast<const float4*>(W)[i];
    __half2 h01, h23;
    h01.x = __float2half(w.x); h01.y = __float2half(w.y);
    h23.x = __float2half(w.z); h23.y = __float2half(w.w);
    __half2* dst = reinterpret_cast<__half2*>(g_Wh + (size_t)4 * i);
    dst[0] = h01; dst[1] = h23;
}

// ---------------- fp16 mma.sync GEMM with fused final rescale epilogue ------
// BM=128, BN=64, warp tile 32x32 -> 2 CTAs/SM. 4-stage cp.async pipeline.
#define BM 128
#define BN 64
#define BK 64
#define RSTR 72                          // 64 data + 8 pad halfs (144B rows)
#define A_STG (BM * RSTR)                // 9216 halfs
#define B_STG (BN * RSTR)                // 4608 halfs
#define NSTAGE 4
#define SMEM_B ((NSTAGE * (A_STG + B_STG)) * 2)   // 110592 bytes

__global__ void __launch_bounds__(256, 2) gemm_fused(
    const float* __restrict__ fv, const float* __restrict__ zeta,
    const float* __restrict__ bias, float* __restrict__ out, int N, int F) {
    extern __shared__ __half sm[];
    __half* As = sm;                        // [NSTAGE][BM][RSTR]
    __half* Bs = sm + NSTAGE * A_STG;       // [NSTAGE][BN][RSTR]
    int tid = threadIdx.x;
    int m0 = blockIdx.y * BM;
    int n0 = blockIdx.x * BN;
    uint32_t asBase = (uint32_t)__cvta_generic_to_shared(As);
    uint32_t bsBase = (uint32_t)__cvta_generic_to_shared(Bs);
    int NK = F / BK;                        // 16

    float acc[2][4][4];
#pragma unroll
    for (int a = 0; a < 2; ++a)
#pragma unroll
        for (int b = 0; b < 4; ++b)
#pragma unroll
            for (int c2 = 0; c2 < 4; ++c2) acc[a][b][c2] = 0.f;

    int wid = tid / 32, lane = tid % 32;
    int warpM = (wid >> 1) * 32;            // 4 warp rows
    int warpN = (wid & 1) * 32;             // 2 warp cols
    int r = lane >> 2, c = lane & 3;

    auto loadAB = [&](int st, int kt) {
#pragma unroll
        for (int it = 0; it < 4; ++it) {    // A: 1024 chunks
            int id = tid + 256 * it;
            int row = id >> 3, ch = id & 7;
            int gr = m0 + row; if (gr > N - 1) gr = N - 1;
            const void* srcA = g_Yh + (size_t)gr * F + kt * BK + ch * 8;
            cp16(asBase + (uint32_t)(st * A_STG + row * RSTR) * 2u + ch * 16u, srcA);
        }
#pragma unroll
        for (int it = 0; it < 2; ++it) {    // B: 512 chunks
            int id = tid + 256 * it;
            int row = id >> 3, ch = id & 7;
            const void* srcB = g_Wh + (size_t)(n0 + row) * F + kt * BK + ch * 8;
            cp16(bsBase + (uint32_t)(st * B_STG + row * RSTR) * 2u + ch * 16u, srcB);
        }
    };

    loadAB(0, 0); cp_commit();
    loadAB(1, 1); cp_commit();
    loadAB(2, 2); cp_commit();
    loadAB(3, 3); cp_commit();

    int l8 = lane & 7, lg = lane >> 3;      // ldmatrix lane grouping

    for (int kt = 0; kt < NK; ++kt) {
        int st = kt % NSTAGE;
        // Commits happen EVERY iteration (empty groups in the tail): before this
        // wait, committed = 4 + kt groups; wait_group 3 leaves at most the 3
        // newest pending => groups 0..kt (this kt's data) are complete.
        cp_wait<3>();
        __syncthreads();
        const __half* At = As + st * A_STG;
        const __half* Bt = Bs + st * B_STG;
#pragma unroll
        for (int ks = 0; ks < 4; ++ks) {    // 4 k16-steps per BK=64
            uint32_t a[2][4], bb[4][2];
#pragma unroll
            for (int mt = 0; mt < 2; ++mt) {
                int arow = warpM + mt * 16 + ((lg & 1) ? 8 : 0) + l8;
                int acol = ks * 16 + ((lg >> 1) ? 8 : 0);
                uint32_t addr = (uint32_t)__cvta_generic_to_shared(At + arow * RSTR + acol);
                asm volatile("ldmatrix.sync.aligned.m8n8.x4.shared.b16 {%0,%1,%2,%3}, [%4];"
                             : "=r"(a[mt][0]), "=r"(a[mt][1]), "=r"(a[mt][2]), "=r"(a[mt][3])
                             : "r"(addr));
            }
#pragma unroll
            for (int pp = 0; pp < 2; ++pp) {
                int brow = warpN + pp * 16 + ((lg >> 1) ? 8 : 0) + l8;
                int bcol = ks * 16 + ((lg & 1) ? 8 : 0);
                uint32_t addr = (uint32_t)__cvta_generic_to_shared(Bt + brow * RSTR + bcol);
                uint32_t r0, r1, r2, r3;
                asm volatile("ldmatrix.sync.aligned.m8n8.x4.shared.b16 {%0,%1,%2,%3}, [%4];"
                             : "=r"(r0), "=r"(r1), "=r"(r2), "=r"(r3) : "r"(addr));
                bb[pp * 2 + 0][0] = r0; bb[pp * 2 + 0][1] = r1;
                bb[pp * 2 + 1][0] = r2; bb[pp * 2 + 1][1] = r3;
            }
#pragma unroll
            for (int mt = 0; mt < 2; ++mt)
#pragma unroll
                for (int nt = 0; nt < 4; ++nt)
                    asm volatile(
                        "mma.sync.aligned.m16n8k16.row.col.f32.f16.f16.f32 "
                        "{%0,%1,%2,%3},{%4,%5,%6,%7},{%8,%9},{%0,%1,%2,%3};\n"
                        : "+f"(acc[mt][nt][0]), "+f"(acc[mt][nt][1]),
                          "+f"(acc[mt][nt][2]), "+f"(acc[mt][nt][3])
                        : "r"(a[mt][0]), "r"(a[mt][1]), "r"(a[mt][2]), "r"(a[mt][3]),
                          "r"(bb[nt][0]), "r"(bb[nt][1]));
        }
        __syncthreads();
        if (kt + NSTAGE < NK) loadAB(st, kt + NSTAGE);
        cp_commit();                         // ALWAYS commit (empty group in tail)
    }
    cp_wait<0>();

    // Fused epilogue. feat is RECOMPUTED from the fv components we already
    // load (saves the 131MB g_feat read):
    //   fv layout at base=(n*F+j)*3: [j,c0][j,c1][j,c2][j+1,c0][j+1,c1][j+1,c2]
    //   feat_j   = ||(v0.x, v0.y, v1.x) + 1e-8||
    //   feat_j+1 = ||(v1.y, v2.x, v2.y) + 1e-8||
#pragma unroll
    for (int mt = 0; mt < 2; ++mt) {
#pragma unroll
        for (int half = 0; half < 2; ++half) {
            int n = m0 + warpM + mt * 16 + r + half * 8;
            if (n >= N) continue;
#pragma unroll
            for (int nt = 0; nt < 4; ++nt) {
                int j = n0 + warpN + nt * 8 + 2 * c;
                float d0 = acc[mt][nt][half * 2 + 0];
                float d1 = acc[mt][nt][half * 2 + 1];
                size_t base = ((size_t)n * F + j) * 3;
                const float2* vp = reinterpret_cast<const float2*>(fv + base);
                float2 v0 = vp[0], v1 = vp[1], v2 = vp[2];
                float xa = v0.x + 1e-8f, ya = v0.y + 1e-8f, za = v1.x + 1e-8f;
                float xb = v1.y + 1e-8f, yb = v2.x + 1e-8f, zb = v2.y + 1e-8f;
                float ft0 = sqrtf(fmaf(xa, xa, fmaf(ya, ya, za * za)));
                float ft1 = sqrtf(fmaf(xb, xb, fmaf(yb, yb, zb * zb)));
                float gt0 = d0 + bias[j];
                float gt1 = d1 + bias[j + 1];
                float s0 = gt0 / (ft0 + zeta[j] + 1e-8f);
                float s1 = gt1 / (ft1 + zeta[j + 1] + 1e-8f);
                float2* op = reinterpret_cast<float2*>(out + base);
                float2 o0, o1, o2;
                o0.x = s0 * v0.x; o0.y = s0 * v0.y;
                o1.x = s0 * v1.x; o1.y = s1 * v1.y;
                o2.x = s1 * v2.x; o2.y = s1 * v2.y;
                op[0] = o0; op[1] = o1; op[2] = o2;
            }
        }
    }
}

// ---------------- launch -----------------------------------------------------
extern "C" void kernel_launch(void* const* d_in, const int* in_sizes, int n_in,
                              void* d_out, int out_size) {
    int o = (n_in >= 9) ? 3 : 2;
    const float* fv    = (const float*)d_in[0];
    const int*   seg   = (const int*)d_in[1];
    const float* alpha = (const float*)d_in[o];
    const float* beta  = (const float*)d_in[o + 1];
    const float* gamma = (const float*)d_in[o + 2];
    const float* zeta  = (const float*)d_in[o + 3];
    const float* W     = (const float*)d_in[o + 4];
    const float* bias  = (const float*)d_in[o + 5];
    int F = in_sizes[o];
    int N = in_sizes[0] / (3 * F);
    float* out = (float*)d_out;

    zero_stats<<<(GMAX * FMAXD + 255) / 256, 256>>>();
    count_nodes<<<(N + 255) / 256, 256>>>(seg, N);

    int npb = 25;   // more CTAs -> better latency hiding (25 | 1000 so blocks
                    // stay within one graph; no mid-loop atomic flushes)
    dim3 g1((F / 4 + 255) / 256, (N + npb - 1) / npb);
    pass1<<<g1, 256>>>(fv, seg, N, F, npb);

    dim3 g2(F / 256, GMAX);
    stats<<<g2, 256>>>(alpha, beta, gamma, F);

    long long yq = (long long)N * (F / 4);
    make_y<<<(unsigned)((yq + 255) / 256), 256>>>(seg, N, F);
    conv_w<<<(F * F / 4 + 255) / 256, 256>>>(W, F * F / 4);

    cudaFuncSetAttribute(gemm_fused, cudaFuncAttributeMaxDynamicSharedMemorySize, SMEM_B);
    dim3 gg(F / BN, (N + BM - 1) / BM);
    gemm_fused<<<gg, 256, SMEM_B>>>(fv, zeta, bias, out, N, F);
}

// round 9
// speedup vs baseline: 1.8544x; 1.0190x over previous
#include <cuda_runtime.h>
#include <cuda_fp16.h>
#include <cstdint>
#include <cstddef>

#define FMAXD 1024
#define GMAX  256
#define MAXN  40960

// ---------------- scratch (static device globals; no runtime allocation) ---
__device__ float  g_feat[(size_t)MAXN * FMAXD];
__device__ __half g_Yh[(size_t)MAXN * FMAXD];
__device__ __half g_Wh[(size_t)FMAXD * FMAXD];
__device__ float  g_sum[GMAX * FMAXD];
__device__ float  g_sq[GMAX * FMAXD];
__device__ float  g_s[GMAX * FMAXD];
__device__ float  g_t[GMAX * FMAXD];
__device__ int    g_cnt[GMAX];

// ---------------- helpers ---------------------------------------------------
__device__ __forceinline__ void cp16(uint32_t dst, const void* src) {
    asm volatile("cp.async.cg.shared.global [%0], [%1], 16;\n" :: "r"(dst), "l"(src));
}
__device__ __forceinline__ void cp_commit() { asm volatile("cp.async.commit_group;\n"); }
template <int n> __device__ __forceinline__ void cp_wait() {
    asm volatile("cp.async.wait_group %0;\n" :: "n"(n));
}
__device__ __forceinline__ void l2_prefetch(const void* p) {
    asm volatile("prefetch.global.L2 [%0];" :: "l"(p));
}

// ---------------- small kernels ---------------------------------------------
__global__ void zero_stats() {
    int i = blockIdx.x * blockDim.x + threadIdx.x;
    if (i < GMAX * FMAXD) { g_sum[i] = 0.f; g_sq[i] = 0.f; }
    if (i < GMAX) g_cnt[i] = 0;
}

__global__ void count_nodes(const int* __restrict__ seg, int N) {
    __shared__ int h[GMAX];
    for (int i = threadIdx.x; i < GMAX; i += blockDim.x) h[i] = 0;
    __syncthreads();
    int i = blockIdx.x * blockDim.x + threadIdx.x;
    if (i < N) atomicAdd(&h[seg[i]], 1);
    __syncthreads();
    for (int i = threadIdx.x; i < GMAX; i += blockDim.x)
        if (h[i]) atomicAdd(&g_cnt[i], h[i]);
}

// Pass 1 (vectorized): each thread owns a feature-quad. 12 contiguous floats
// = 4 features x 3 comps = 3 x float4 loads, 1 x float4 feat store.
__global__ void pass1(const float* __restrict__ fv, const int* __restrict__ seg,
                      int N, int F, int npb) {
    int q  = blockIdx.x * blockDim.x + threadIdx.x;   // feature quad
    if (q >= F / 4) return;
    int n0 = blockIdx.y * npb;
    if (n0 >= N) return;
    int nend = min(n0 + npb, N);
    float s1[4] = {0.f, 0.f, 0.f, 0.f};
    float s2[4] = {0.f, 0.f, 0.f, 0.f};
    int curg = seg[n0];
    int f0 = 4 * q;
    for (int n = n0; n < nend; ++n) {
        int g = seg[n];
        if (g != curg) {
#pragma unroll
            for (int k = 0; k < 4; ++k) {
                atomicAdd(&g_sum[curg * F + f0 + k], s1[k]);
                atomicAdd(&g_sq[curg * F + f0 + k], s2[k]);
                s1[k] = 0.f; s2[k] = 0.f;
            }
            curg = g;
        }
        const float4* p = reinterpret_cast<const float4*>(fv + ((size_t)n * F + f0) * 3);
        float4 a = p[0], b = p[1], c = p[2];
        float x0 = a.x + 1e-8f, y0 = a.y + 1e-8f, z0 = a.z + 1e-8f;
        float x1 = a.w + 1e-8f, y1 = b.x + 1e-8f, z1 = b.y + 1e-8f;
        float x2 = b.z + 1e-8f, y2 = b.w + 1e-8f, z2 = c.x + 1e-8f;
        float x3 = c.y + 1e-8f, y3 = c.z + 1e-8f, z3 = c.w + 1e-8f;
        float4 ft;
        ft.x = sqrtf(fmaf(x0, x0, fmaf(y0, y0, z0 * z0)));
        ft.y = sqrtf(fmaf(x1, x1, fmaf(y1, y1, z1 * z1)));
        ft.z = sqrtf(fmaf(x2, x2, fmaf(y2, y2, z2 * z2)));
        ft.w = sqrtf(fmaf(x3, x3, fmaf(y3, y3, z3 * z3)));
        reinterpret_cast<float4*>(g_feat + (size_t)n * F + f0)[0] = ft;
        s1[0] += ft.x; s2[0] = fmaf(ft.x, ft.x, s2[0]);
        s1[1] += ft.y; s2[1] = fmaf(ft.y, ft.y, s2[1]);
        s1[2] += ft.z; s2[2] = fmaf(ft.z, ft.z, s2[2]);
        s1[3] += ft.w; s2[3] = fmaf(ft.w, ft.w, s2[3]);
    }
#pragma unroll
    for (int k = 0; k < 4; ++k) {
        atomicAdd(&g_sum[curg * F + f0 + k], s1[k]);
        atomicAdd(&g_sq[curg * F + f0 + k], s2[k]);
    }
}

// Per-(g,f) affine coefficients: y = feat*s + t
__global__ void stats(const float* __restrict__ alpha, const float* __restrict__ beta,
                      const float* __restrict__ gamma, int F) {
    int f = blockIdx.x * blockDim.x + threadIdx.x;
    int g = blockIdx.y;
    int c = g_cnt[g];
    if (c == 0) return;
    float invc = 1.f / (float)c;
    size_t idx = (size_t)g * F + f;
    float u  = g_sum[idx] * invc;
    float u2 = alpha[f] * u;
    float m2 = g_sq[idx] * invc;
    float sigma = m2 - 2.f * u2 * u + u2 * u2;
    float sn = sqrtf(sigma + 1e-6f);
    float iv = 1.f / (sn + 1e-6f);
    float sv = gamma[f] * iv;
    g_s[idx] = sv;
    g_t[idx] = fmaf(-u2, sv, beta[f]);
}

// Y = feat*s + t, cast to fp16
__global__ void make_y(const int* __restrict__ seg, int N, int F) {
    int q = F / 4;
    long long i = (long long)blockIdx.x * blockDim.x + threadIdx.x;
    if (i >= (long long)N * q) return;
    int n = (int)(i / q);
    int j = (int)(i % q);
    int g = seg[n];
    float4 ft = reinterpret_cast<const float4*>(g_feat)[(size_t)n * q + j];
    float4 sv = reinterpret_cast<const float4*>(g_s)[(size_t)g * q + j];
    float4 tv = reinterpret_cast<const float4*>(g_t)[(size_t)g * q + j];
    __half2 y01, y23;
    y01.x = __float2half(fmaf(ft.x, sv.x, tv.x));
    y01.y = __float2half(fmaf(ft.y, sv.y, tv.y));
    y23.x = __float2half(fmaf(ft.z, sv.z, tv.z));
    y23.y = __float2half(fmaf(ft.w, sv.w, tv.w));
    __half2* dst = reinterpret_cast<__half2*>(g_Yh + (size_t)n * F + 4 * j);
    dst[0] = y01; dst[1] = y23;
}

__global__ void conv_w(const float* __restrict__ W, int total4) {
    int i = blockIdx.x * blockDim.x + threadIdx.x;
    if (i >= total4) return;
    float4 w = reinterpret_cast<const float4*>(W)[i];
    __half2 h01, h23;
    h01.x = __float2half(w.x); h01.y = __float2half(w.y);
    h23.x = __float2half(w.z); h23.y = __float2half(w.w);
    __half2* dst = reinterpret_cast<__half2*>(g_Wh + (size_t)4 * i);
    dst[0] = h01; dst[1] = h23;
}

// ---------------- fp16 mma.sync GEMM with fused final rescale epilogue ------
// BM=128, BN=64, warp tile 32x32 -> 2 CTAs/SM. 4-stage, SINGLE-sync mainloop.
#define BM 128
#define BN 64
#define BK 64
#define RSTR 72                          // 64 data + 8 pad halfs (144B rows)
#define A_STG (BM * RSTR)                // 9216 halfs
#define B_STG (BN * RSTR)                // 4608 halfs
#define NSTAGE 4
#define SMEM_B ((NSTAGE * (A_STG + B_STG)) * 2)   // 110592 bytes

__global__ void __launch_bounds__(256, 2) gemm_fused(
    const float* __restrict__ fv, const float* __restrict__ zeta,
    const float* __restrict__ bias, float* __restrict__ out, int N, int F) {
    extern __shared__ __half sm[];
    __half* As = sm;                        // [NSTAGE][BM][RSTR]
    __half* Bs = sm + NSTAGE * A_STG;       // [NSTAGE][BN][RSTR]
    int tid = threadIdx.x;
    int m0 = blockIdx.y * BM;
    int n0 = blockIdx.x * BN;
    uint32_t asBase = (uint32_t)__cvta_generic_to_shared(As);
    uint32_t bsBase = (uint32_t)__cvta_generic_to_shared(Bs);
    int NK = F / BK;                        // 16

    float acc[2][4][4];
#pragma unroll
    for (int a = 0; a < 2; ++a)
#pragma unroll
        for (int b = 0; b < 4; ++b)
#pragma unroll
            for (int c2 = 0; c2 < 4; ++c2) acc[a][b][c2] = 0.f;

    int wid = tid / 32, lane = tid % 32;
    int warpM = (wid >> 1) * 32;            // 4 warp rows
    int warpN = (wid & 1) * 32;             // 2 warp cols
    int r = lane >> 2, c = lane & 3;

    auto loadAB = [&](int st, int kt) {
#pragma unroll
        for (int it = 0; it < 4; ++it) {    // A: 1024 chunks
            int id = tid + 256 * it;
            int row = id >> 3, ch = id & 7;
            int gr = m0 + row; if (gr > N - 1) gr = N - 1;
            const void* srcA = g_Yh + (size_t)gr * F + kt * BK + ch * 8;
            cp16(asBase + (uint32_t)(st * A_STG + row * RSTR) * 2u + ch * 16u, srcA);
        }
#pragma unroll
        for (int it = 0; it < 2; ++it) {    // B: 512 chunks
            int id = tid + 256 * it;
            int row = id >> 3, ch = id & 7;
            const void* srcB = g_Wh + (size_t)(n0 + row) * F + kt * BK + ch * 8;
            cp16(bsBase + (uint32_t)(st * B_STG + row * RSTR) * 2u + ch * 16u, srcB);
        }
    };

    // Prologue: NSTAGE-1 = 3 stages
    loadAB(0, 0); cp_commit();
    loadAB(1, 1); cp_commit();
    loadAB(2, 2); cp_commit();

    int l8 = lane & 7, lg = lane >> 3;      // ldmatrix lane grouping

    for (int kt = 0; kt < NK; ++kt) {
        int st = kt & 3;
        // committed groups before this wait = 3 + kt; wait_group 2 => groups
        // 0..kt complete (tile kt landed).
        cp_wait<2>();
        __syncthreads();
        // Immediately issue loads for tile kt+3 into stage (kt+3)&3 = (kt-1)&3:
        // that stage was consumed at iteration kt-1, and every warp passed this
        // barrier only after finishing kt-1's compute => safe. ONE sync per kt.
        {
            int kn = kt + NSTAGE - 1;
            if (kn < NK) loadAB(kn & 3, kn);
            cp_commit();                     // always commit (empty in tail)
        }
        if (kt == 4) {
            // L2-prefetch this block's epilogue fv footprint (128 rows x 768B).
            // 768 lines of 128B; 3 per thread.
#pragma unroll
            for (int i = 0; i < 3; ++i) {
                int id = tid + 256 * i;      // 0..767
                int row = id / 6, seg6 = id % 6;
                int gr = m0 + row; if (gr > N - 1) gr = N - 1;
                const char* p = reinterpret_cast<const char*>(
                    fv + ((size_t)gr * F + n0) * 3) + seg6 * 128;
                l2_prefetch(p);
            }
        }
        const __half* At = As + st * A_STG;
        const __half* Bt = Bs + st * B_STG;
#pragma unroll
        for (int ks = 0; ks < 4; ++ks) {    // 4 k16-steps per BK=64
            uint32_t a[2][4], bb[4][2];
#pragma unroll
            for (int mt = 0; mt < 2; ++mt) {
                int arow = warpM + mt * 16 + ((lg & 1) ? 8 : 0) + l8;
                int acol = ks * 16 + ((lg >> 1) ? 8 : 0);
                uint32_t addr = (uint32_t)__cvta_generic_to_shared(At + arow * RSTR + acol);
                asm volatile("ldmatrix.sync.aligned.m8n8.x4.shared.b16 {%0,%1,%2,%3}, [%4];"
                             : "=r"(a[mt][0]), "=r"(a[mt][1]), "=r"(a[mt][2]), "=r"(a[mt][3])
                             : "r"(addr));
            }
#pragma unroll
            for (int pp = 0; pp < 2; ++pp) {
                int brow = warpN + pp * 16 + ((lg >> 1) ? 8 : 0) + l8;
                int bcol = ks * 16 + ((lg & 1) ? 8 : 0);
                uint32_t addr = (uint32_t)__cvta_generic_to_shared(Bt + brow * RSTR + bcol);
                uint32_t r0, r1, r2, r3;
                asm volatile("ldmatrix.sync.aligned.m8n8.x4.shared.b16 {%0,%1,%2,%3}, [%4];"
                             : "=r"(r0), "=r"(r1), "=r"(r2), "=r"(r3) : "r"(addr));
                bb[pp * 2 + 0][0] = r0; bb[pp * 2 + 0][1] = r1;
                bb[pp * 2 + 1][0] = r2; bb[pp * 2 + 1][1] = r3;
            }
#pragma unroll
            for (int mt = 0; mt < 2; ++mt)
#pragma unroll
                for (int nt = 0; nt < 4; ++nt)
                    asm volatile(
                        "mma.sync.aligned.m16n8k16.row.col.f32.f16.f16.f32 "
                        "{%0,%1,%2,%3},{%4,%5,%6,%7},{%8,%9},{%0,%1,%2,%3};\n"
                        : "+f"(acc[mt][nt][0]), "+f"(acc[mt][nt][1]),
                          "+f"(acc[mt][nt][2]), "+f"(acc[mt][nt][3])
                        : "r"(a[mt][0]), "r"(a[mt][1]), "r"(a[mt][2]), "r"(a[mt][3]),
                          "r"(bb[nt][0]), "r"(bb[nt][1]));
        }
    }
    cp_wait<0>();

    // Fused epilogue. feat recomputed from the fv components we already load:
    //   fv at base=(n*F+j)*3: [j,c0][j,c1][j,c2][j+1,c0][j+1,c1][j+1,c2]
#pragma unroll
    for (int mt = 0; mt < 2; ++mt) {
#pragma unroll
        for (int half = 0; half < 2; ++half) {
            int n = m0 + warpM + mt * 16 + r + half * 8;
            if (n >= N) continue;
#pragma unroll
            for (int nt = 0; nt < 4; ++nt) {
                int j = n0 + warpN + nt * 8 + 2 * c;
                float d0 = acc[mt][nt][half * 2 + 0];
                float d1 = acc[mt][nt][half * 2 + 1];
                size_t base = ((size_t)n * F + j) * 3;
                const float2* vp = reinterpret_cast<const float2*>(fv + base);
                float2 v0 = vp[0], v1 = vp[1], v2 = vp[2];
                float xa = v0.x + 1e-8f, ya = v0.y + 1e-8f, za = v1.x + 1e-8f;
                float xb = v1.y + 1e-8f, yb = v2.x + 1e-8f, zb = v2.y + 1e-8f;
                float ft0 = sqrtf(fmaf(xa, xa, fmaf(ya, ya, za * za)));
                float ft1 = sqrtf(fmaf(xb, xb, fmaf(yb, yb, zb * zb)));
                float gt0 = d0 + bias[j];
                float gt1 = d1 + bias[j + 1];
                float s0 = gt0 / (ft0 + zeta[j] + 1e-8f);
                float s1 = gt1 / (ft1 + zeta[j + 1] + 1e-8f);
                float2* op = reinterpret_cast<float2*>(out + base);
                float2 o0, o1, o2;
                o0.x = s0 * v0.x; o0.y = s0 * v0.y;
                o1.x = s0 * v1.x; o1.y = s1 * v1.y;
                o2.x = s1 * v2.x; o2.y = s1 * v2.y;
                op[0] = o0; op[1] = o1; op[2] = o2;
            }
        }
    }
}

// ---------------- launch -----------------------------------------------------
extern "C" void kernel_launch(void* const* d_in, const int* in_sizes, int n_in,
                              void* d_out, int out_size) {
    int o = (n_in >= 9) ? 3 : 2;
    const float* fv    = (const float*)d_in[0];
    const int*   seg   = (const int*)d_in[1];
    const float* alpha = (const float*)d_in[o];
    const float* beta  = (const float*)d_in[o + 1];
    const float* gamma = (const float*)d_in[o + 2];
    const float* zeta  = (const float*)d_in[o + 3];
    const float* W     = (const float*)d_in[o + 4];
    const float* bias  = (const float*)d_in[o + 5];
    int F = in_sizes[o];
    int N = in_sizes[0] / (3 * F);
    float* out = (float*)d_out;

    zero_stats<<<(GMAX * FMAXD + 255) / 256, 256>>>();
    count_nodes<<<(N + 255) / 256, 256>>>(seg, N);

    int npb = 25;   // 25 | 1000: each block stays within one graph
    dim3 g1((F / 4 + 255) / 256, (N + npb - 1) / npb);
    pass1<<<g1, 256>>>(fv, seg, N, F, npb);

    dim3 g2(F / 256, GMAX);
    stats<<<g2, 256>>>(alpha, beta, gamma, F);

    long long yq = (long long)N * (F / 4);
    make_y<<<(unsigned)((yq + 255) / 256), 256>>>(seg, N, F);
    conv_w<<<(F * F / 4 + 255) / 256, 256>>>(W, F * F / 4);

    cudaFuncSetAttribute(gemm_fused, cudaFuncAttributeMaxDynamicSharedMemorySize, SMEM_B);
    dim3 gg(F / BN, (N + BM - 1) / BM);
    gemm_fused<<<gg, 256, SMEM_B>>>(fv, zeta, bias, out, N, F);
}

// round 10
// speedup vs baseline: 1.8674x; 1.0070x over previous
#include <cuda_runtime.h>
#include <cuda_fp16.h>
#include <cstdint>
#include <cstddef>

#define FMAXD 1024
#define GMAX  256
#define MAXN  40960

// ---------------- scratch (static device globals; no runtime allocation) ---
__device__ float  g_feat[(size_t)MAXN * FMAXD];
__device__ __half g_Yh[(size_t)MAXN * FMAXD];
__device__ __half g_Wh[(size_t)FMAXD * FMAXD];
__device__ float  g_sum[GMAX * FMAXD];
__device__ float  g_sq[GMAX * FMAXD];
__device__ float  g_s[GMAX * FMAXD];
__device__ float  g_t[GMAX * FMAXD];
__device__ int    g_cnt[GMAX];

// ---------------- helpers ---------------------------------------------------
__device__ __forceinline__ void cp16(uint32_t dst, const void* src) {
    asm volatile("cp.async.cg.shared.global [%0], [%1], 16;\n" :: "r"(dst), "l"(src));
}
__device__ __forceinline__ void cp_commit() { asm volatile("cp.async.commit_group;\n"); }
template <int n> __device__ __forceinline__ void cp_wait() {
    asm volatile("cp.async.wait_group %0;\n" :: "n"(n));
}
__device__ __forceinline__ void l2_prefetch(const void* p) {
    asm volatile("prefetch.global.L2 [%0];" :: "l"(p));
}

// ---------------- small kernels ---------------------------------------------
__global__ void zero_stats() {
    int i = blockIdx.x * blockDim.x + threadIdx.x;
    if (i < GMAX * FMAXD) { g_sum[i] = 0.f; g_sq[i] = 0.f; }
    if (i < GMAX) g_cnt[i] = 0;
}

__global__ void count_nodes(const int* __restrict__ seg, int N) {
    __shared__ int h[GMAX];
    for (int i = threadIdx.x; i < GMAX; i += blockDim.x) h[i] = 0;
    __syncthreads();
    int i = blockIdx.x * blockDim.x + threadIdx.x;
    if (i < N) atomicAdd(&h[seg[i]], 1);
    __syncthreads();
    for (int i = threadIdx.x; i < GMAX; i += blockDim.x)
        if (h[i]) atomicAdd(&g_cnt[i], h[i]);
}

// Pass 1 (vectorized): each thread owns a feature-quad.
__global__ void pass1(const float* __restrict__ fv, const int* __restrict__ seg,
                      int N, int F, int npb) {
    int q  = blockIdx.x * blockDim.x + threadIdx.x;   // feature quad
    if (q >= F / 4) return;
    int n0 = blockIdx.y * npb;
    if (n0 >= N) return;
    int nend = min(n0 + npb, N);
    float s1[4] = {0.f, 0.f, 0.f, 0.f};
    float s2[4] = {0.f, 0.f, 0.f, 0.f};
    int curg = seg[n0];
    int f0 = 4 * q;
    for (int n = n0; n < nend; ++n) {
        int g = seg[n];
        if (g != curg) {
#pragma unroll
            for (int k = 0; k < 4; ++k) {
                atomicAdd(&g_sum[curg * F + f0 + k], s1[k]);
                atomicAdd(&g_sq[curg * F + f0 + k], s2[k]);
                s1[k] = 0.f; s2[k] = 0.f;
            }
            curg = g;
        }
        const float4* p = reinterpret_cast<const float4*>(fv + ((size_t)n * F + f0) * 3);
        float4 a = p[0], b = p[1], c = p[2];
        float x0 = a.x + 1e-8f, y0 = a.y + 1e-8f, z0 = a.z + 1e-8f;
        float x1 = a.w + 1e-8f, y1 = b.x + 1e-8f, z1 = b.y + 1e-8f;
        float x2 = b.z + 1e-8f, y2 = b.w + 1e-8f, z2 = c.x + 1e-8f;
        float x3 = c.y + 1e-8f, y3 = c.z + 1e-8f, z3 = c.w + 1e-8f;
        float4 ft;
        ft.x = sqrtf(fmaf(x0, x0, fmaf(y0, y0, z0 * z0)));
        ft.y = sqrtf(fmaf(x1, x1, fmaf(y1, y1, z1 * z1)));
        ft.z = sqrtf(fmaf(x2, x2, fmaf(y2, y2, z2 * z2)));
        ft.w = sqrtf(fmaf(x3, x3, fmaf(y3, y3, z3 * z3)));
        reinterpret_cast<float4*>(g_feat + (size_t)n * F + f0)[0] = ft;
        s1[0] += ft.x; s2[0] = fmaf(ft.x, ft.x, s2[0]);
        s1[1] += ft.y; s2[1] = fmaf(ft.y, ft.y, s2[1]);
        s1[2] += ft.z; s2[2] = fmaf(ft.z, ft.z, s2[2]);
        s1[3] += ft.w; s2[3] = fmaf(ft.w, ft.w, s2[3]);
    }
#pragma unroll
    for (int k = 0; k < 4; ++k) {
        atomicAdd(&g_sum[curg * F + f0 + k], s1[k]);
        atomicAdd(&g_sq[curg * F + f0 + k], s2[k]);
    }
}

// Per-(g,f) affine coefficients: y = feat*s + t
__global__ void stats(const float* __restrict__ alpha, const float* __restrict__ beta,
                      const float* __restrict__ gamma, int F) {
    int f = blockIdx.x * blockDim.x + threadIdx.x;
    int g = blockIdx.y;
    int c = g_cnt[g];
    if (c == 0) return;
    float invc = 1.f / (float)c;
    size_t idx = (size_t)g * F + f;
    float u  = g_sum[idx] * invc;
    float u2 = alpha[f] * u;
    float m2 = g_sq[idx] * invc;
    float sigma = m2 - 2.f * u2 * u + u2 * u2;
    float sn = sqrtf(sigma + 1e-6f);
    float iv = 1.f / (sn + 1e-6f);
    float sv = gamma[f] * iv;
    g_s[idx] = sv;
    g_t[idx] = fmaf(-u2, sv, beta[f]);
}

// Y = feat*s + t, cast to fp16
__global__ void make_y(const int* __restrict__ seg, int N, int F) {
    int q = F / 4;
    long long i = (long long)blockIdx.x * blockDim.x + threadIdx.x;
    if (i >= (long long)N * q) return;
    int n = (int)(i / q);
    int j = (int)(i % q);
    int g = seg[n];
    float4 ft = reinterpret_cast<const float4*>(g_feat)[(size_t)n * q + j];
    float4 sv = reinterpret_cast<const float4*>(g_s)[(size_t)g * q + j];
    float4 tv = reinterpret_cast<const float4*>(g_t)[(size_t)g * q + j];
    __half2 y01, y23;
    y01.x = __float2half(fmaf(ft.x, sv.x, tv.x));
    y01.y = __float2half(fmaf(ft.y, sv.y, tv.y));
    y23.x = __float2half(fmaf(ft.z, sv.z, tv.z));
    y23.y = __float2half(fmaf(ft.w, sv.w, tv.w));
    __half2* dst = reinterpret_cast<__half2*>(g_Yh + (size_t)n * F + 4 * j);
    dst[0] = y01; dst[1] = y23;
}

__global__ void conv_w(const float* __restrict__ W, int total4) {
    int i = blockIdx.x * blockDim.x + threadIdx.x;
    if (i >= total4) return;
    float4 w = reinterpret_cast<const float4*>(W)[i];
    __half2 h01, h23;
    h01.x = __float2half(w.x); h01.y = __float2half(w.y);
    h23.x = __float2half(w.z); h23.y = __float2half(w.w);
    __half2* dst = reinterpret_cast<__half2*>(g_Wh + (size_t)4 * i);
    dst[0] = h01; dst[1] = h23;
}

// ---------------- fp16 mma.sync GEMM with fused final rescale epilogue ------
// BM=256, BN=128 halves GEMM L2 traffic vs BM=128/BN=64 (Y transits L2
// 8x instead of 16x; W 125x instead of 250x). 512 threads, warp tile 64x32,
// 4-stage single-sync pipeline. 1 CTA/SM (221KB smem) but 16 warps.
#define BM 256
#define BN 128
#define BK 64
#define RSTR 72                          // 64 data + 8 pad halfs (144B rows)
#define A_STG (BM * RSTR)                // 18432 halfs
#define B_STG (BN * RSTR)                // 9216 halfs
#define NSTAGE 4
#define SMEM_B ((NSTAGE * (A_STG + B_STG)) * 2)   // 221184 bytes
#define NTHR 512

__global__ void __launch_bounds__(NTHR, 1) gemm_fused(
    const float* __restrict__ fv, const float* __restrict__ zeta,
    const float* __restrict__ bias, float* __restrict__ out, int N, int F) {
    extern __shared__ __half sm[];
    __half* As = sm;                        // [NSTAGE][BM][RSTR]
    __half* Bs = sm + NSTAGE * A_STG;       // [NSTAGE][BN][RSTR]
    int tid = threadIdx.x;
    int m0 = blockIdx.y * BM;
    int n0 = blockIdx.x * BN;
    uint32_t asBase = (uint32_t)__cvta_generic_to_shared(As);
    uint32_t bsBase = (uint32_t)__cvta_generic_to_shared(Bs);
    int NK = F / BK;                        // 16

    float acc[4][4][4];
#pragma unroll
    for (int a = 0; a < 4; ++a)
#pragma unroll
        for (int b = 0; b < 4; ++b)
#pragma unroll
            for (int c2 = 0; c2 < 4; ++c2) acc[a][b][c2] = 0.f;

    int wid = tid / 32, lane = tid % 32;
    int warpM = (wid >> 2) * 64;            // 4 warp rows (64 m each)
    int warpN = (wid & 3) * 32;             // 4 warp cols (32 n each)
    int r = lane >> 2, c = lane & 3;

    auto loadAB = [&](int st, int kt) {
#pragma unroll
        for (int it = 0; it < 4; ++it) {    // A: 2048 chunks / 512 thr
            int id = tid + NTHR * it;
            int row = id >> 3, ch = id & 7;
            int gr = m0 + row; if (gr > N - 1) gr = N - 1;
            const void* srcA = g_Yh + (size_t)gr * F + kt * BK + ch * 8;
            cp16(asBase + (uint32_t)(st * A_STG + row * RSTR) * 2u + ch * 16u, srcA);
        }
#pragma unroll
        for (int it = 0; it < 2; ++it) {    // B: 1024 chunks / 512 thr
            int id = tid + NTHR * it;
            int row = id >> 3, ch = id & 7;
            const void* srcB = g_Wh + (size_t)(n0 + row) * F + kt * BK + ch * 8;
            cp16(bsBase + (uint32_t)(st * B_STG + row * RSTR) * 2u + ch * 16u, srcB);
        }
    };

    // Prologue: NSTAGE-1 = 3 stages
    loadAB(0, 0); cp_commit();
    loadAB(1, 1); cp_commit();
    loadAB(2, 2); cp_commit();

    int l8 = lane & 7, lg = lane >> 3;      // ldmatrix lane grouping

    for (int kt = 0; kt < NK; ++kt) {
        int st = kt & 3;
        // committed = 3 + kt before this wait; wait_group 2 => tiles 0..kt done.
        cp_wait<2>();
        __syncthreads();
        // Issue tile kt+3 into stage (kt-1)&3 (consumed last iteration; all
        // warps are past it once they pass this barrier). ONE sync per kt.
        {
            int kn = kt + NSTAGE - 1;
            if (kn < NK) loadAB(kn & 3, kn);
            cp_commit();                     // always commit (empty in tail)
        }
        if (kt == 4) {
            // L2-prefetch epilogue fv footprint: 256 rows x 128 feats x 12B
            // = 3072 lines of 128B; 6 per thread.
#pragma unroll
            for (int i = 0; i < 6; ++i) {
                int id = tid + NTHR * i;     // 0..3071
                int row = id / 12, sl = id % 12;
                int gr = m0 + row; if (gr > N - 1) gr = N - 1;
                const char* p = reinterpret_cast<const char*>(
                    fv + ((size_t)gr * F + n0) * 3) + sl * 128;
                l2_prefetch(p);
            }
        }
        const __half* At = As + st * A_STG;
        const __half* Bt = Bs + st * B_STG;
#pragma unroll
        for (int ks = 0; ks < 4; ++ks) {    // 4 k16-steps per BK=64
            uint32_t a[4][4], bb[4][2];
#pragma unroll
            for (int mt = 0; mt < 4; ++mt) {
                int arow = warpM + mt * 16 + ((lg & 1) ? 8 : 0) + l8;
                int acol = ks * 16 + ((lg >> 1) ? 8 : 0);
                uint32_t addr = (uint32_t)__cvta_generic_to_shared(At + arow * RSTR + acol);
                asm volatile("ldmatrix.sync.aligned.m8n8.x4.shared.b16 {%0,%1,%2,%3}, [%4];"
                             : "=r"(a[mt][0]), "=r"(a[mt][1]), "=r"(a[mt][2]), "=r"(a[mt][3])
                             : "r"(addr));
            }
#pragma unroll
            for (int pp = 0; pp < 2; ++pp) {
                int brow = warpN + pp * 16 + ((lg >> 1) ? 8 : 0) + l8;
                int bcol = ks * 16 + ((lg & 1) ? 8 : 0);
                uint32_t addr = (uint32_t)__cvta_generic_to_shared(Bt + brow * RSTR + bcol);
                uint32_t r0, r1, r2, r3;
                asm volatile("ldmatrix.sync.aligned.m8n8.x4.shared.b16 {%0,%1,%2,%3}, [%4];"
                             : "=r"(r0), "=r"(r1), "=r"(r2), "=r"(r3) : "r"(addr));
                bb[pp * 2 + 0][0] = r0; bb[pp * 2 + 0][1] = r1;
                bb[pp * 2 + 1][0] = r2; bb[pp * 2 + 1][1] = r3;
            }
#pragma unroll
            for (int mt = 0; mt < 4; ++mt)
#pragma unroll
                for (int nt = 0; nt < 4; ++nt)
                    asm volatile(
                        "mma.sync.aligned.m16n8k16.row.col.f32.f16.f16.f32 "
                        "{%0,%1,%2,%3},{%4,%5,%6,%7},{%8,%9},{%0,%1,%2,%3};\n"
                        : "+f"(acc[mt][nt][0]), "+f"(acc[mt][nt][1]),
                          "+f"(acc[mt][nt][2]), "+f"(acc[mt][nt][3])
                        : "r"(a[mt][0]), "r"(a[mt][1]), "r"(a[mt][2]), "r"(a[mt][3]),
                          "r"(bb[nt][0]), "r"(bb[nt][1]));
        }
    }
    cp_wait<0>();

    // Fused epilogue. feat recomputed from the fv components we already load:
    //   fv at base=(n*F+j)*3: [j,c0][j,c1][j,c2][j+1,c0][j+1,c1][j+1,c2]
#pragma unroll
    for (int mt = 0; mt < 4; ++mt) {
#pragma unroll
        for (int half = 0; half < 2; ++half) {
            int n = m0 + warpM + mt * 16 + r + half * 8;
            if (n >= N) continue;
#pragma unroll
            for (int nt = 0; nt < 4; ++nt) {
                int j = n0 + warpN + nt * 8 + 2 * c;
                float d0 = acc[mt][nt][half * 2 + 0];
                float d1 = acc[mt][nt][half * 2 + 1];
                size_t base = ((size_t)n * F + j) * 3;
                const float2* vp = reinterpret_cast<const float2*>(fv + base);
                float2 v0 = vp[0], v1 = vp[1], v2 = vp[2];
                float xa = v0.x + 1e-8f, ya = v0.y + 1e-8f, za = v1.x + 1e-8f;
                float xb = v1.y + 1e-8f, yb = v2.x + 1e-8f, zb = v2.y + 1e-8f;
                float ft0 = sqrtf(fmaf(xa, xa, fmaf(ya, ya, za * za)));
                float ft1 = sqrtf(fmaf(xb, xb, fmaf(yb, yb, zb * zb)));
                float gt0 = d0 + bias[j];
                float gt1 = d1 + bias[j + 1];
                float s0 = gt0 / (ft0 + zeta[j] + 1e-8f);
                float s1 = gt1 / (ft1 + zeta[j + 1] + 1e-8f);
                float2* op = reinterpret_cast<float2*>(out + base);
                float2 o0, o1, o2;
                o0.x = s0 * v0.x; o0.y = s0 * v0.y;
                o1.x = s0 * v1.x; o1.y = s1 * v1.y;
                o2.x = s1 * v2.x; o2.y = s1 * v2.y;
                op[0] = o0; op[1] = o1; op[2] = o2;
            }
        }
    }
}

// ---------------- launch -----------------------------------------------------
extern "C" void kernel_launch(void* const* d_in, const int* in_sizes, int n_in,
                              void* d_out, int out_size) {
    int o = (n_in >= 9) ? 3 : 2;
    const float* fv    = (const float*)d_in[0];
    const int*   seg   = (const int*)d_in[1];
    const float* alpha = (const float*)d_in[o];
    const float* beta  = (const float*)d_in[o + 1];
    const float* gamma = (const float*)d_in[o + 2];
    const float* zeta  = (const float*)d_in[o + 3];
    const float* W     = (const float*)d_in[o + 4];
    const float* bias  = (const float*)d_in[o + 5];
    int F = in_sizes[o];
    int N = in_sizes[0] / (3 * F);
    float* out = (float*)d_out;

    zero_stats<<<(GMAX * FMAXD + 255) / 256, 256>>>();
    count_nodes<<<(N + 255) / 256, 256>>>(seg, N);

    int npb = 25;   // 25 | 1000: each block stays within one graph
    dim3 g1((F / 4 + 255) / 256, (N + npb - 1) / npb);
    pass1<<<g1, 256>>>(fv, seg, N, F, npb);

    dim3 g2(F / 256, GMAX);
    stats<<<g2, 256>>>(alpha, beta, gamma, F);

    long long yq = (long long)N * (F / 4);
    make_y<<<(unsigned)((yq + 255) / 256), 256>>>(seg, N, F);
    conv_w<<<(F * F / 4 + 255) / 256, 256>>>(W, F * F / 4);

    cudaFuncSetAttribute(gemm_fused, cudaFuncAttributeMaxDynamicSharedMemorySize, SMEM_B);
    dim3 gg(F / BN, (N + BM - 1) / BM);
    gemm_fused<<<gg, NTHR, SMEM_B>>>(fv, zeta, bias, out, N, F);
}